// round 8
// baseline (speedup 1.0000x reference)
#include <cuda_runtime.h>
#include <math.h>

#define NG    2048
#define HPIX  128
#define WPIX  128
#define NPIX  (HPIX*WPIX)
#define FOCAL 128.0f
#define NEARP 0.3f
#define EPSV  1e-4f

#define NSEG  8            // one depth segment per warp
#define GPS   (NG/NSEG)    // 256 gaussians per segment
#define TILW  8
#define TILH  4
#define NTX   (WPIX/TILW)  // 16
#define NTY   (HPIX/TILH)  // 32
#define NTILE (NTX*NTY)    // 512 blocks

// ---- scratch (device globals; no allocation allowed) ----
__device__ float  g_r[NG];
__device__ float4 g_K[NG];   // u, v, hx, hy      (unsorted)
__device__ float4 g_P[NG];   // ia, ib, ic, opa_eff
__device__ float4 g_Q[NG];   // r, g, b, 0
__device__ float4 s_K[NG];   // sorted by depth
__device__ float4 s_P[NG];
__device__ float4 s_Q[NG];

__device__ __forceinline__ float sigmoidf(float x) {
    return 1.0f / (1.0f + expf(-x));
}

// ---------------- K1: per-gaussian preprocessing ----------------
__global__ void k_prep(const float* __restrict__ pos,
                       const float* __restrict__ rgb,
                       const float* __restrict__ opa,
                       const float* __restrict__ quat,
                       const float* __restrict__ scale,
                       const float* __restrict__ rot,
                       const float* __restrict__ tran)
{
    int i = blockIdx.x * blockDim.x + threadIdx.x;
    if (i >= NG) return;

    float R00=rot[0],R01=rot[1],R02=rot[2];
    float R10=rot[3],R11=rot[4],R12=rot[5];
    float R20=rot[6],R21=rot[7],R22=rot[8];

    float px = pos[3*i+0], py = pos[3*i+1], pz = pos[3*i+2];
    float x = R00*px + R01*py + R02*pz + tran[0];
    float y = R10*px + R11*py + R12*pz + tran[1];
    float z = R20*px + R21*py + R22*pz + tran[2];

    float r  = sqrtf(x*x + y*y + z*z);
    float iz = 1.0f / z;
    float u  = x * iz;
    float v  = y * iz;

    float J00 = iz,        J02 = -x * iz * iz;
    float J11 = iz,        J12 = -y * iz * iz;
    float W00 = J00*R00 + J02*R20;
    float W01 = J00*R01 + J02*R21;
    float W02 = J00*R02 + J02*R22;
    float W10 = J11*R10 + J12*R20;
    float W11 = J11*R11 + J12*R21;
    float W12 = J11*R12 + J12*R22;

    float qw = quat[4*i+0], qx = quat[4*i+1], qy = quat[4*i+2], qz = quat[4*i+3];
    float qn = rsqrtf(qw*qw + qx*qx + qy*qy + qz*qz);
    qw*=qn; qx*=qn; qy*=qn; qz*=qn;
    float M00 = 1.f - 2.f*(qy*qy + qz*qz);
    float M01 = 2.f*(qx*qy - qw*qz);
    float M02 = 2.f*(qx*qz + qw*qy);
    float M10 = 2.f*(qx*qy + qw*qz);
    float M11 = 1.f - 2.f*(qx*qx + qz*qz);
    float M12 = 2.f*(qy*qz - qw*qx);
    float M20 = 2.f*(qx*qz - qw*qy);
    float M21 = 2.f*(qy*qz + qw*qx);
    float M22 = 1.f - 2.f*(qx*qx + qy*qy);

    float s0 = fabsf(scale[3*i+0]) + 1e-4f;
    float s1 = fabsf(scale[3*i+1]) + 1e-4f;
    float s2 = fabsf(scale[3*i+2]) + 1e-4f;

    float A00=M00*s0, A01=M01*s1, A02=M02*s2;
    float A10=M10*s0, A11=M11*s1, A12=M12*s2;
    float A20=M20*s0, A21=M21*s1, A22=M22*s2;
    float c00 = A00*A00 + A01*A01 + A02*A02;
    float c01 = A00*A10 + A01*A11 + A02*A12;
    float c02 = A00*A20 + A01*A21 + A02*A22;
    float c11 = A10*A10 + A11*A11 + A12*A12;
    float c12 = A10*A20 + A11*A21 + A12*A22;
    float c22 = A20*A20 + A21*A21 + A22*A22;

    float t00 = c00*W00 + c01*W01 + c02*W02;
    float t01 = c01*W00 + c11*W01 + c12*W02;
    float t02 = c02*W00 + c12*W01 + c22*W02;
    float t10 = c00*W10 + c01*W11 + c02*W12;
    float t11 = c01*W10 + c11*W11 + c12*W12;
    float t12 = c02*W10 + c12*W11 + c22*W12;

    float a = W00*t00 + W01*t01 + W02*t02 + EPSV;
    float b = W00*t10 + W01*t11 + W02*t12;
    float c = W10*t10 + W11*t11 + W12*t12 + EPSV;

    float det  = a*c - b*b;
    float idet = 1.0f / det;
    float ia =  c * idet;
    float ib = -b * idet;
    float ic =  a * idet;

    float rr = sigmoidf(rgb[3*i+0]);
    float rg = sigmoidf(rgb[3*i+1]);
    float rb = sigmoidf(rgb[3*i+2]);
    float op = sigmoidf(opa[i]);
    float opa_eff = (z > NEARP) ? op : 0.0f;

    // conservative screen-space AABB: cull where alpha = opa*exp(-q/2) < ~1.5e-8
    float hx, hy;
    if (opa_eff < 1.5e-8f) {
        hx = -1e30f; hy = -1e30f;   // never overlaps any tile
    } else {
        float qc = 2.0f * (logf(opa_eff) + 18.0f);
        qc = fmaxf(qc, 0.0f);
        hx = sqrtf(qc * a);
        hy = sqrtf(qc * c);
    }

    g_r[i] = r;
    g_K[i] = make_float4(u, v, hx, hy);
    g_P[i] = make_float4(ia, ib, ic, opa_eff);
    g_Q[i] = make_float4(rr, rg, rb, 0.0f);
}

// ---------------- K2: stable rank-sort (8-way split scan) ----------------
// 64 blocks x 256 threads; 8 threads per gaussian, each scans 256 keys.
__global__ void __launch_bounds__(256) k_sort()
{
    __shared__ float sr[NG];
    for (int j = threadIdx.x; j < NG; j += blockDim.x) sr[j] = g_r[j];
    __syncthreads();

    int t   = blockIdx.x * 256 + threadIdx.x;   // 0..16383
    int i   = t >> 3;                            // gaussian 0..2047
    int sub = t & 7;                             // sub-scanner 0..7
    float ri = sr[i];

    int rank = 0;
    int j0 = sub * (NG/8);
#pragma unroll 8
    for (int j = j0; j < j0 + NG/8; j++) {
        float rj = sr[j];
        rank += (rj < ri) || (rj == ri && j < i);   // stable (matches argsort)
    }
    // reduce the 8 partials (contiguous lanes of one warp)
    rank += __shfl_down_sync(0xffffffffu, rank, 4, 8);
    rank += __shfl_down_sync(0xffffffffu, rank, 2, 8);
    rank += __shfl_down_sync(0xffffffffu, rank, 1, 8);

    if (sub == 0) {
        s_K[rank] = g_K[i];
        s_P[rank] = g_P[i];
        s_Q[rank] = g_Q[i];
    }
}

// ---------------- K3: fused tiled render + segment combine ----------------
// Block = 256 threads = 8 warps. Warp w composites depth segment w
// ([w*256, w*256+256)) for an 8x4 pixel tile; segments combined in shared.
__global__ void __launch_bounds__(256) k_render(float* __restrict__ out)
{
    int tile = blockIdx.x;
    int tx = tile & (NTX-1), ty = tile >> 4;
    int w    = threadIdx.x >> 5;
    int lane = threadIdx.x & 31;

    int col = tx * TILW + (lane & 7);
    int row = ty * TILH + (lane >> 3);
    float pxf = ((float)col - 63.5f) / FOCAL;
    float pyf = ((float)row - 63.5f) / FOCAL;
    // tile pixel-center bounds
    float x0 = ((float)(tx * TILW)            - 63.5f) / FOCAL;
    float x1 = ((float)(tx * TILW + TILW - 1) - 63.5f) / FOCAL;
    float y0 = ((float)(ty * TILH)            - 63.5f) / FOCAL;
    float y1 = ((float)(ty * TILH + TILH - 1) - 63.5f) / FOCAL;

    float T = 1.0f, cr = 0.0f, cg = 0.0f, cb = 0.0f;
    int base = w * GPS;

#pragma unroll 2
    for (int c0 = 0; c0 < GPS; c0 += 32) {
        int j = base + c0 + lane;
        float4 K = s_K[j];                       // u, v, hx, hy

        bool keep = (K.x + K.z >= x0) & (K.x - K.z <= x1) &
                    (K.y + K.w >= y0) & (K.y - K.w <= y1);

        unsigned m = __ballot_sync(0xffffffffu, keep);
        float4 P, Q;
        if (keep) {                               // only survivors fetch full params
            P = s_P[j];
            Q = s_Q[j];
        }
        while (m) {
            int src = __ffs(m) - 1;
            m &= m - 1;
            float su = __shfl_sync(0xffffffffu, K.x, src);
            float sv = __shfl_sync(0xffffffffu, K.y, src);
            float ia = __shfl_sync(0xffffffffu, P.x, src);
            float ib = __shfl_sync(0xffffffffu, P.y, src);
            float ic = __shfl_sync(0xffffffffu, P.z, src);
            float op = __shfl_sync(0xffffffffu, P.w, src);
            float qr = __shfl_sync(0xffffffffu, Q.x, src);
            float qg = __shfl_sync(0xffffffffu, Q.y, src);
            float qb = __shfl_sync(0xffffffffu, Q.z, src);

            float dx = pxf - su;
            float dy = pyf - sv;
            float q  = dx * (ia * dx + 2.0f * ib * dy) + ic * dy * dy;
            float e  = __expf(-0.5f * q);
            float alpha = fminf(op * e, 0.99f);
            float wgt = T * alpha;
            cr = fmaf(wgt, qr, cr);
            cg = fmaf(wgt, qg, cg);
            cb = fmaf(wgt, qb, cb);
            T -= wgt;                             // T *= (1 - alpha)
        }
    }

    // combine the 8 depth segments (front-to-back: warp 0 first)
    __shared__ float4 part[NSEG][32];
    part[w][lane] = make_float4(cr, cg, cb, T);
    __syncthreads();

    if (w == 0) {
        float Tt = 1.0f, ar = 0.0f, ag = 0.0f, ab = 0.0f;
#pragma unroll
        for (int s = 0; s < NSEG; s++) {
            float4 p = part[s][lane];
            ar += Tt * p.x;
            ag += Tt * p.y;
            ab += Tt * p.z;
            Tt *= p.w;
        }
        int pix = row * WPIX + col;
        out[3*pix+0] = ar;
        out[3*pix+1] = ag;
        out[3*pix+2] = ab;
    }
}

extern "C" void kernel_launch(void* const* d_in, const int* in_sizes, int n_in,
                              void* d_out, int out_size)
{
    const float* pos   = (const float*)d_in[0];
    const float* rgb   = (const float*)d_in[1];
    const float* opa   = (const float*)d_in[2];
    const float* quat  = (const float*)d_in[3];
    const float* scale = (const float*)d_in[4];
    const float* rot   = (const float*)d_in[5];
    const float* tran  = (const float*)d_in[6];
    float* out = (float*)d_out;

    k_prep<<<NG/128, 128>>>(pos, rgb, opa, quat, scale, rot, tran);
    k_sort<<<64, 256>>>();
    k_render<<<NTILE, 256>>>(out);
}